// round 5
// baseline (speedup 1.0000x reference)
#include <cuda_runtime.h>
#include <cstdint>

// y[N] = x[N,H] @ w[H] + bias,  w[h] = FP4_TABLE[codes[h]] * absmax[h>>6]
// N = 32768, H = 4096. HBM-streaming GEMV.
// x is streamed through a 3-stage cp.async (LDGSTS) smem pipeline: MLP is set
// by pipeline depth (2 outstanding 8KB stages x 5 blocks/SM = 80KB in flight),
// not by ptxas register allocation (which defeated register batching in R1/R3).

#define H_DIM   4096
#define RPB     8                    // rows per block (1 per warp)
#define THREADS (RPB * 32)
#define CHUNK   256                  // floats per row per stage
#define NCHUNK  (H_DIM / CHUNK)      // 16
#define STAGES  3
#define ROW_F4  (CHUNK / 4)          // 64 float4 per row per stage
#define STAGE_F4 (RPB * ROW_F4)      // 512 float4 per stage (8KB)

__device__ __constant__ float c_fp4_tab[16] = {
    0.0f, 0.0052083333f, 0.6666667f, 1.0f, 0.3333333f, 0.5f, 0.16666667f, 0.25f,
    -0.0f, -0.0052083333f, -0.6666667f, -1.0f, -0.3333333f, -0.5f, -0.16666667f, -0.25f
};

__device__ __forceinline__ void cp_async16(void* smem_dst, const void* gmem_src) {
    unsigned dst = (unsigned)__cvta_generic_to_shared(smem_dst);
    asm volatile("cp.async.cg.shared.global [%0], [%1], 16;"
                 :: "r"(dst), "l"(gmem_src));
}

__global__ __launch_bounds__(THREADS)
void fp4_gemv_kernel(const float* __restrict__ x,
                     const int*   __restrict__ codes,
                     const float* __restrict__ absmax,
                     const float* __restrict__ bias,
                     float*       __restrict__ y,
                     int N)
{
    __shared__ float  w_s[H_DIM];                 // 16 KB
    __shared__ float4 xs[STAGES][STAGE_F4];       // 3 x 8 KB

    const int tid  = threadIdx.x;
    const int warp = tid >> 5;
    const int lane = tid & 31;
    const int rowbase = blockIdx.x * RPB;

    // Dequantize weight vector (codes/absmax are tiny, L2-resident).
    for (int i = tid; i < H_DIM; i += THREADS)
        w_s[i] = c_fp4_tab[codes[i] & 15] * absmax[i >> 6];
    const float b = __ldg(bias);

    // ---- cp.async stage issue: chunk c -> stage buffer ----
    // Stage layout: [row][64 float4]. Each thread copies 2 float4.
    auto issue = [&](int c, float4* stage) {
        #pragma unroll
        for (int k = 0; k < 2; k++) {
            int q   = tid + k * THREADS;          // [0, 512)
            int row = q >> 6;                     // q / ROW_F4
            int col = q & 63;
            int r   = min(rowbase + row, N - 1);  // clamp (N is a multiple of 8 here)
            const float4* src = reinterpret_cast<const float4*>(
                x + (size_t)r * H_DIM + (size_t)c * CHUNK) + col;
            cp_async16(&stage[q], src);
        }
        asm volatile("cp.async.commit_group;" ::: "memory");
    };

    issue(0, xs[0]);
    issue(1, xs[1]);

    const int myrow = rowbase + warp;
    float acc0 = 0.0f, acc1 = 0.0f;

    #pragma unroll
    for (int c = 0; c < NCHUNK; c++) {
        // Oldest outstanding group (chunk c) must be complete.
        asm volatile("cp.async.wait_group 1;" ::: "memory");
        __syncthreads();

        const float4* xrow = &xs[c % STAGES][warp * ROW_F4];
        const float4* wrow = reinterpret_cast<const float4*>(w_s) + c * ROW_F4;

        #pragma unroll
        for (int j = 0; j < 2; j++) {
            float4 xv = xrow[lane + j * 32];
            float4 wv = wrow[lane + j * 32];
            acc0 = fmaf(xv.x, wv.x, acc0);
            acc1 = fmaf(xv.y, wv.y, acc1);
            acc0 = fmaf(xv.z, wv.z, acc0);
            acc1 = fmaf(xv.w, wv.w, acc1);
        }

        // Refill: stage (c+2)%3 was last read in iter c-1; everyone passed this
        // iter's barrier already, so no second barrier is needed.
        if (c + 2 < NCHUNK)
            issue(c + 2, xs[(c + 2) % STAGES]);
        else
            asm volatile("cp.async.commit_group;" ::: "memory");  // keep group count exact
    }

    float acc = acc0 + acc1;
    #pragma unroll
    for (int off = 16; off > 0; off >>= 1)
        acc += __shfl_xor_sync(0xFFFFFFFFu, acc, off);

    if (lane == 0 && myrow < N)
        y[myrow] = acc + b;
}

extern "C" void kernel_launch(void* const* d_in, const int* in_sizes, int n_in,
                              void* d_out, int out_size)
{
    const float* x      = (const float*)d_in[0];   // [N, H] fp32
    const int*   codes  = (const int*)  d_in[1];   // [1, H] int32
    const float* absmax = (const float*)d_in[2];   // [1, H/64] fp32
    const float* bias   = (const float*)d_in[3];   // [1] fp32
    float*       y      = (float*)d_out;           // [N, 1] fp32

    const int N = in_sizes[0] / H_DIM;             // 32768
    const int grid = (N + RPB - 1) / RPB;

    fp4_gemv_kernel<<<grid, THREADS>>>(x, codes, absmax, bias, y, N);
}

// round 6
// speedup vs baseline: 1.0568x; 1.0568x over previous
#include <cuda_runtime.h>
#include <cstdint>

// y[N] = x[N,H] @ w[H] + bias,  w[h] = FP4_TABLE[codes[h]] * absmax[h>>6]
// N = 32768, H = 4096. HBM-streaming GEMV.
//
// R5 diagnosis: every compiler-scheduled variant ends up with effective MLP=1
// per warp (ptxas places each load's consumer right behind it), giving
// ~1.7MB in flight chip-wide and ~4.8TB/s. Here the 8-deep load batch is
// forced with asm volatile (unreorderable), so SASS carries 8 back-to-back
// LDG.E.128 per group -> 8x the in-flight bytes per warp.

#define H_DIM 4096
#define RPB   8                      // rows per block, 1 per warp
#define THREADS (RPB * 32)

__device__ __constant__ float c_fp4_tab[16] = {
    0.0f, 0.0052083333f, 0.6666667f, 1.0f, 0.3333333f, 0.5f, 0.16666667f, 0.25f,
    -0.0f, -0.0052083333f, -0.6666667f, -1.0f, -0.3333333f, -0.5f, -0.16666667f, -0.25f
};

// Unreorderable 16B streaming load: forces SASS ordering (load batches stay batched).
__device__ __forceinline__ float4 ldg_cs_f4(const float4* p) {
    float4 v;
    asm volatile("ld.global.cs.v4.f32 {%0,%1,%2,%3}, [%4];"
                 : "=f"(v.x), "=f"(v.y), "=f"(v.z), "=f"(v.w)
                 : "l"(p));
    return v;
}

__global__ __launch_bounds__(THREADS)
void fp4_gemv_kernel(const float* __restrict__ x,
                     const int*   __restrict__ codes,
                     const float* __restrict__ absmax,
                     const float* __restrict__ bias,
                     float*       __restrict__ y,
                     int N)
{
    __shared__ float w_s[H_DIM];     // 16 KB

    // Dequantize the tiny weight vector into shared memory (codes/absmax L2-resident).
    for (int i = threadIdx.x; i < H_DIM; i += THREADS)
        w_s[i] = c_fp4_tab[codes[i] & 15] * absmax[i >> 6];
    const float b = __ldg(bias);
    __syncthreads();

    const int warp = threadIdx.x >> 5;
    const int lane = threadIdx.x & 31;
    const int row  = blockIdx.x * RPB + warp;
    if (row >= N) return;

    const float4* __restrict__ xr = reinterpret_cast<const float4*>(x + (size_t)row * H_DIM);
    const float4* __restrict__ ws = reinterpret_cast<const float4*>(w_s);

    // 1024 float4 per row; 32 per lane as 4 groups of 8.
    // The 8 loads of each group are asm volatile -> guaranteed back-to-back in SASS.
    float acc0 = 0.0f, acc1 = 0.0f;

    #pragma unroll
    for (int g = 0; g < 4; g++) {
        const float4* base = xr + g * 256 + lane;
        float4 v0 = ldg_cs_f4(base + 0 * 32);
        float4 v1 = ldg_cs_f4(base + 1 * 32);
        float4 v2 = ldg_cs_f4(base + 2 * 32);
        float4 v3 = ldg_cs_f4(base + 3 * 32);
        float4 v4 = ldg_cs_f4(base + 4 * 32);
        float4 v5 = ldg_cs_f4(base + 5 * 32);
        float4 v6 = ldg_cs_f4(base + 6 * 32);
        float4 v7 = ldg_cs_f4(base + 7 * 32);

        const float4* wb = ws + g * 256 + lane;
        float4 w;
        #define ACC(V, J)                           \
            w = wb[(J) * 32];                       \
            acc0 = fmaf((V).x, w.x, acc0);          \
            acc1 = fmaf((V).y, w.y, acc1);          \
            acc0 = fmaf((V).z, w.z, acc0);          \
            acc1 = fmaf((V).w, w.w, acc1);
        ACC(v0, 0) ACC(v1, 1) ACC(v2, 2) ACC(v3, 3)
        ACC(v4, 4) ACC(v5, 5) ACC(v6, 6) ACC(v7, 7)
        #undef ACC
    }

    float acc = acc0 + acc1;
    #pragma unroll
    for (int off = 16; off > 0; off >>= 1)
        acc += __shfl_xor_sync(0xFFFFFFFFu, acc, off);

    if (lane == 0)
        y[row] = acc + b;
}

extern "C" void kernel_launch(void* const* d_in, const int* in_sizes, int n_in,
                              void* d_out, int out_size)
{
    const float* x      = (const float*)d_in[0];   // [N, H] fp32
    const int*   codes  = (const int*)  d_in[1];   // [1, H] int32
    const float* absmax = (const float*)d_in[2];   // [1, H/64] fp32
    const float* bias   = (const float*)d_in[3];   // [1] fp32
    float*       y      = (float*)d_out;           // [N, 1] fp32

    const int N = in_sizes[0] / H_DIM;             // 32768
    const int grid = (N + RPB - 1) / RPB;

    fp4_gemv_kernel<<<grid, THREADS>>>(x, codes, absmax, bias, y, N);
}